// round 6
// baseline (speedup 1.0000x reference)
#include <cuda_runtime.h>
#include <cuda_fp16.h>
#include <stdint.h>

#define N_NODES 100000
#define N_EDGES 1600000
#define F_IN  64
#define F_HID 64
#define F_OUT 32

#define SCAN_B 98   // 98 * 1024 >= N_NODES

// ---------------- static device scratch ----------------
__device__ float  g_dinv[N_NODES];
__device__ __half g_xws [N_NODES * F_HID];   // (x@W1)*dinv, fp16
__device__ float  g_h   [N_NODES * F_HID];   // relu hidden (fp32)
__device__ __half g_hws [N_NODES * F_OUT];   // (h@W2)*dinv, fp16
__device__ int    g_cnt [N_NODES];
__device__ int    g_off [N_NODES + 1];
__device__ int    g_cur [N_NODES];
__device__ int    g_csr [N_EDGES];
__device__ int    g_bsum[SCAN_B];
__device__ int    g_bbase[SCAN_B];
__device__ int    g_is64;

// ---------------- edge index fetch ----------------
__device__ __forceinline__ void get_edge(const int* __restrict__ w, int is64,
                                         int e, int& s, int& d) {
    if (is64) {
        s = w[2 * e];
        d = w[2 * N_EDGES + 2 * e];
    } else {
        s = w[e];
        d = w[N_EDGES + e];
    }
}

// zero counts + (block 0, warp 0) dtype detection
__global__ void k_zero(const int* __restrict__ w) {
    int i = blockIdx.x * blockDim.x + threadIdx.x;
    if (i < N_NODES) g_cnt[i] = 0;
    if (blockIdx.x == 0 && threadIdx.x < 32) {
        int lane = threadIdx.x;
        int nz = (w[2 * lane + 1] != 0) || (w[2 * (lane + 32) + 1] != 0);
        unsigned any = __ballot_sync(0xffffffffu, nz);
        if (lane == 0) g_is64 = (any == 0u);
    }
}

__global__ void k_hist(const int* __restrict__ ew) {
    int e = blockIdx.x * blockDim.x + threadIdx.x;
    if (e >= N_EDGES) return;
    int s, d;
    get_edge(ew, g_is64, e, s, d);
    atomicAdd(&g_cnt[d], 1);
}

// ---------------- coalesced 3-pass scan ----------------
__global__ void __launch_bounds__(1024) k_scan_red() {
    int i = blockIdx.x * 1024 + threadIdx.x;
    int v = (i < N_NODES) ? g_cnt[i] : 0;
#pragma unroll
    for (int o = 16; o > 0; o >>= 1) v += __shfl_down_sync(0xffffffffu, v, o);
    __shared__ int ws[32];
    int lane = threadIdx.x & 31, wid = threadIdx.x >> 5;
    if (lane == 0) ws[wid] = v;
    __syncthreads();
    if (wid == 0) {
        int s = ws[lane];
#pragma unroll
        for (int o = 16; o > 0; o >>= 1) s += __shfl_down_sync(0xffffffffu, s, o);
        if (lane == 0) g_bsum[blockIdx.x] = s;
    }
}

__global__ void __launch_bounds__(128) k_scan_base() {
    __shared__ int sh[128];
    int t = threadIdx.x;
    int v = (t < SCAN_B) ? g_bsum[t] : 0;
    sh[t] = v;
    __syncthreads();
    for (int o = 1; o < 128; o <<= 1) {
        int u = (t >= o) ? sh[t - o] : 0;
        __syncthreads();
        sh[t] += u;
        __syncthreads();
    }
    if (t < SCAN_B) g_bbase[t] = sh[t] - v;
    if (t == 0) g_off[N_NODES] = N_EDGES;
}

__global__ void __launch_bounds__(1024) k_scan_write() {
    int t = threadIdx.x;
    int i = blockIdx.x * 1024 + t;
    int lane = t & 31, wid = t >> 5;
    int c = (i < N_NODES) ? g_cnt[i] : 0;

    int inc = c;
#pragma unroll
    for (int o = 1; o < 32; o <<= 1) {
        int u = __shfl_up_sync(0xffffffffu, inc, o);
        if (lane >= o) inc += u;
    }
    __shared__ int wpre[32];
    if (lane == 31) wpre[wid] = inc;
    __syncthreads();
    if (wid == 0) {
        int s = wpre[lane];
        int sinc = s;
#pragma unroll
        for (int o = 1; o < 32; o <<= 1) {
            int u = __shfl_up_sync(0xffffffffu, sinc, o);
            if (lane >= o) sinc += u;
        }
        wpre[lane] = sinc - s;
    }
    __syncthreads();

    if (i < N_NODES) {
        int exc = inc - c + wpre[wid] + g_bbase[blockIdx.x];
        g_off[i] = exc;
        g_cur[i] = exc;
        g_dinv[i] = rsqrtf((float)c + 1.0f);
    }
}

__global__ void k_fill(const int* __restrict__ ew) {
    int e = blockIdx.x * blockDim.x + threadIdx.x;
    if (e >= N_EDGES) return;
    int s, d;
    get_edge(ew, g_is64, e, s, d);
    int slot = atomicAdd(&g_cur[d], 1);
    g_csr[slot] = s;
}

// ---------------- GEMM1: xws = fp16((x @ W1) * dinv) ----------------
__global__ void __launch_bounds__(256) k_gemm1(const float* __restrict__ x,
                                               const float* __restrict__ W) {
    __shared__ float4 ws[F_IN * (F_HID / 4)];
    int tid = threadIdx.x;
    for (int i = tid; i < F_IN * (F_HID / 4); i += 256)
        ws[i] = ((const float4*)W)[i];
    __syncthreads();

    int row = blockIdx.x * 256 + tid;
    if (row >= N_NODES) return;

    float4 acc[16];
#pragma unroll
    for (int j = 0; j < 16; j++) acc[j] = make_float4(0.f, 0.f, 0.f, 0.f);

    const float4* xr = (const float4*)(x + (size_t)row * F_IN);
#pragma unroll
    for (int kk = 0; kk < 16; kk++) {
        float4 xv = __ldg(xr + kk);
        float xs[4] = {xv.x, xv.y, xv.z, xv.w};
#pragma unroll
        for (int t = 0; t < 4; t++) {
            int k = kk * 4 + t;
            float xk = xs[t];
#pragma unroll
            for (int j = 0; j < 16; j++) {
                float4 w4 = ws[k * 16 + j];
                acc[j].x = fmaf(xk, w4.x, acc[j].x);
                acc[j].y = fmaf(xk, w4.y, acc[j].y);
                acc[j].z = fmaf(xk, w4.z, acc[j].z);
                acc[j].w = fmaf(xk, w4.w, acc[j].w);
            }
        }
    }
    float s = g_dinv[row];
    __half2 hrow[32];
#pragma unroll
    for (int j = 0; j < 16; j++) {
        hrow[2 * j]     = __floats2half2_rn(acc[j].x * s, acc[j].y * s);
        hrow[2 * j + 1] = __floats2half2_rn(acc[j].z * s, acc[j].w * s);
    }
    uint4* o = (uint4*)(g_xws + (size_t)row * F_HID);
    const uint4* hp = (const uint4*)hrow;
#pragma unroll
    for (int j = 0; j < 8; j++) o[j] = hp[j];
}

// ---------------- aggregate layer 1 + hidden epilogue (warp per node) ----------
// int4 broadcast index loads: 1 LDG per 4 edges
__global__ void __launch_bounds__(256) k_agg1(const float* __restrict__ b1) {
    int node = (blockIdx.x * 256 + threadIdx.x) >> 5;
    int lane = threadIdx.x & 31;
    if (node >= N_NODES) return;

    int k   = g_off[node];
    int end = g_off[node + 1];
    int col = lane * 2;

    float2 acc0 = make_float2(0.f, 0.f);
    float2 acc1 = make_float2(0.f, 0.f);

    // align k to 4
    while (k < end && (k & 3)) {
        int s = __ldg(g_csr + k);
        float2 f = __half22float2(*(const __half2*)(g_xws + (size_t)s * F_HID + col));
        acc0.x += f.x; acc0.y += f.y;
        k++;
    }
    // 8-edge chunks: 2x int4 index loads + 8 gathers
    for (; k + 8 <= end; k += 8) {
        int4 ia = __ldg((const int4*)(g_csr + k));
        int4 ib = __ldg((const int4*)(g_csr + k) + 1);
        int idx[8] = {ia.x, ia.y, ia.z, ia.w, ib.x, ib.y, ib.z, ib.w};
        __half2 v[8];
#pragma unroll
        for (int j = 0; j < 8; j++)
            v[j] = *(const __half2*)(g_xws + (size_t)idx[j] * F_HID + col);
#pragma unroll
        for (int j = 0; j < 8; j += 2) {
            float2 f0 = __half22float2(v[j]);
            float2 f1 = __half22float2(v[j + 1]);
            acc0.x += f0.x; acc0.y += f0.y;
            acc1.x += f1.x; acc1.y += f1.y;
        }
    }
    if (k + 4 <= end) {
        int4 ia = __ldg((const int4*)(g_csr + k));
        int idx[4] = {ia.x, ia.y, ia.z, ia.w};
        __half2 v[4];
#pragma unroll
        for (int j = 0; j < 4; j++)
            v[j] = *(const __half2*)(g_xws + (size_t)idx[j] * F_HID + col);
        float2 f0 = __half22float2(v[0]), f1 = __half22float2(v[1]);
        float2 f2 = __half22float2(v[2]), f3 = __half22float2(v[3]);
        acc0.x += f0.x + f2.x; acc0.y += f0.y + f2.y;
        acc1.x += f1.x + f3.x; acc1.y += f1.y + f3.y;
        k += 4;
    }
    for (; k < end; k++) {
        int s = __ldg(g_csr + k);
        float2 f = __half22float2(*(const __half2*)(g_xws + (size_t)s * F_HID + col));
        acc0.x += f.x; acc0.y += f.y;
    }

    float2 self = __half22float2(*(const __half2*)(g_xws + (size_t)node * F_HID + col));
    float sc = g_dinv[node];
    float2 b = ((const float2*)b1)[lane];
    float2 r;
    r.x = fmaxf(sc * (acc0.x + acc1.x + self.x) + b.x, 0.f);
    r.y = fmaxf(sc * (acc0.y + acc1.y + self.y) + b.y, 0.f);
    *(float2*)(g_h + (size_t)node * F_HID + col) = r;
}

// ---------------- GEMM2: hws = fp16((h @ W2) * dinv) ----------------
__global__ void __launch_bounds__(256) k_gemm2(const float* __restrict__ W) {
    __shared__ float4 ws[F_HID * (F_OUT / 4)];
    int tid = threadIdx.x;
    for (int i = tid; i < F_HID * (F_OUT / 4); i += 256)
        ws[i] = ((const float4*)W)[i];
    __syncthreads();

    int row = blockIdx.x * 256 + tid;
    if (row >= N_NODES) return;

    float4 acc[8];
#pragma unroll
    for (int j = 0; j < 8; j++) acc[j] = make_float4(0.f, 0.f, 0.f, 0.f);

    const float4* hr = (const float4*)(g_h + (size_t)row * F_HID);
#pragma unroll
    for (int kk = 0; kk < 16; kk++) {
        float4 hv = __ldg(hr + kk);
        float hs[4] = {hv.x, hv.y, hv.z, hv.w};
#pragma unroll
        for (int t = 0; t < 4; t++) {
            int k = kk * 4 + t;
            float hk = hs[t];
#pragma unroll
            for (int j = 0; j < 8; j++) {
                float4 w4 = ws[k * 8 + j];
                acc[j].x = fmaf(hk, w4.x, acc[j].x);
                acc[j].y = fmaf(hk, w4.y, acc[j].y);
                acc[j].z = fmaf(hk, w4.z, acc[j].z);
                acc[j].w = fmaf(hk, w4.w, acc[j].w);
            }
        }
    }
    float s = g_dinv[row];
    __half2 hrow[16];
#pragma unroll
    for (int j = 0; j < 8; j++) {
        hrow[2 * j]     = __floats2half2_rn(acc[j].x * s, acc[j].y * s);
        hrow[2 * j + 1] = __floats2half2_rn(acc[j].z * s, acc[j].w * s);
    }
    uint4* o = (uint4*)(g_hws + (size_t)row * F_OUT);
    const uint4* hp = (const uint4*)hrow;
#pragma unroll
    for (int j = 0; j < 4; j++) o[j] = hp[j];
}

// ---------------- aggregate layer 2: TWO nodes per warp (16 lanes each) --------
__global__ void __launch_bounds__(256) k_agg2(const float* __restrict__ b2,
                                              float* __restrict__ out) {
    int warp = (blockIdx.x * 256 + threadIdx.x) >> 5;
    int half = (threadIdx.x >> 4) & 1;
    int sub  = threadIdx.x & 15;
    int node = warp * 2 + half;
    if (node >= N_NODES) return;

    int k   = g_off[node];
    int end = g_off[node + 1];
    int col = sub * 2;

    float2 acc0 = make_float2(0.f, 0.f);
    float2 acc1 = make_float2(0.f, 0.f);

    while (k < end && (k & 3)) {
        int s = __ldg(g_csr + k);
        float2 f = __half22float2(*(const __half2*)(g_hws + (size_t)s * F_OUT + col));
        acc0.x += f.x; acc0.y += f.y;
        k++;
    }
    for (; k + 8 <= end; k += 8) {
        int4 ia = __ldg((const int4*)(g_csr + k));
        int4 ib = __ldg((const int4*)(g_csr + k) + 1);
        int idx[8] = {ia.x, ia.y, ia.z, ia.w, ib.x, ib.y, ib.z, ib.w};
        __half2 v[8];
#pragma unroll
        for (int j = 0; j < 8; j++)
            v[j] = *(const __half2*)(g_hws + (size_t)idx[j] * F_OUT + col);
#pragma unroll
        for (int j = 0; j < 8; j += 2) {
            float2 f0 = __half22float2(v[j]);
            float2 f1 = __half22float2(v[j + 1]);
            acc0.x += f0.x; acc0.y += f0.y;
            acc1.x += f1.x; acc1.y += f1.y;
        }
    }
    if (k + 4 <= end) {
        int4 ia = __ldg((const int4*)(g_csr + k));
        int idx[4] = {ia.x, ia.y, ia.z, ia.w};
        __half2 v[4];
#pragma unroll
        for (int j = 0; j < 4; j++)
            v[j] = *(const __half2*)(g_hws + (size_t)idx[j] * F_OUT + col);
        float2 f0 = __half22float2(v[0]), f1 = __half22float2(v[1]);
        float2 f2 = __half22float2(v[2]), f3 = __half22float2(v[3]);
        acc0.x += f0.x + f2.x; acc0.y += f0.y + f2.y;
        acc1.x += f1.x + f3.x; acc1.y += f1.y + f3.y;
        k += 4;
    }
    for (; k < end; k++) {
        int s = __ldg(g_csr + k);
        float2 f = __half22float2(*(const __half2*)(g_hws + (size_t)s * F_OUT + col));
        acc0.x += f.x; acc0.y += f.y;
    }

    float2 self = __half22float2(*(const __half2*)(g_hws + (size_t)node * F_OUT + col));
    float sc = g_dinv[node];
    float2 b = ((const float2*)b2)[sub];
    float2 r;
    r.x = sc * (acc0.x + acc1.x + self.x) + b.x;
    r.y = sc * (acc0.y + acc1.y + self.y) + b.y;
    *(float2*)(out + (size_t)node * F_OUT + col) = r;
}

// ---------------- launch ----------------
extern "C" void kernel_launch(void* const* d_in, const int* in_sizes, int n_in,
                              void* d_out, int out_size) {
    const float* x  = (const float*)d_in[0];
    const int*   ew = (const int*)d_in[1];
    const float* W1 = (const float*)d_in[2];
    const float* b1 = (const float*)d_in[3];
    const float* W2 = (const float*)d_in[4];
    const float* b2 = (const float*)d_in[5];
    float* out = (float*)d_out;

    const int T = 256;

    k_zero<<<(N_NODES + T - 1) / T, T>>>(ew);
    k_hist<<<(N_EDGES + T - 1) / T, T>>>(ew);
    k_scan_red<<<SCAN_B, 1024>>>();
    k_scan_base<<<1, 128>>>();
    k_scan_write<<<SCAN_B, 1024>>>();
    k_fill<<<(N_EDGES + T - 1) / T, T>>>(ew);

    k_gemm1<<<(N_NODES + T - 1) / T, T>>>(x, W1);
    k_agg1<<<(N_NODES * 32 + T - 1) / T, T>>>(b1);

    k_gemm2<<<(N_NODES + T - 1) / T, T>>>(W2);
    k_agg2<<<(N_NODES * 16 + T - 1) / T, T>>>(b2, out);
}

// round 7
// speedup vs baseline: 1.0345x; 1.0345x over previous
#include <cuda_runtime.h>
#include <cuda_fp16.h>
#include <stdint.h>

#define N_NODES 100000
#define N_EDGES 1600000
#define F_IN  64
#define F_HID 64
#define F_OUT 32

#define SCAN_B 98   // 98 * 1024 >= N_NODES; 98 <= 148 SMs -> single wave

// ---------------- static device scratch ----------------
__device__ float  g_dinv[N_NODES];
__device__ __half g_xws [N_NODES * F_HID];   // (x@W1)*dinv, fp16
__device__ float  g_h   [N_NODES * F_HID];   // relu hidden (fp32)
__device__ __half g_hws [N_NODES * F_OUT];   // (h@W2)*dinv, fp16
__device__ int    g_cnt [N_NODES];           // BSS-zero; re-zeroed each call by scan
__device__ int    g_off [N_NODES + 1];
__device__ int    g_cur [N_NODES];
__device__ int    g_csr [N_EDGES];
__device__ int    g_scanval [SCAN_B];
__device__ int    g_scanflag[SCAN_B];        // BSS-zero; reset by last block
__device__ int    g_done;                    // BSS-zero; reset by last block

// per-block inline dtype detection: int64 layout (values<2^31) => odd words zero
__device__ __forceinline__ int detect64_t0(const int* __restrict__ w) {
    int nz = 0;
#pragma unroll
    for (int j = 1; j < 16; j += 2) nz |= w[j];
    return nz == 0;
}

// ---------------- histogram over dst (+ per-block detect) ----------------
__global__ void k_hist(const int* __restrict__ ew) {
    __shared__ int s64;
    if (threadIdx.x == 0) s64 = detect64_t0(ew);
    __syncthreads();
    int e = blockIdx.x * blockDim.x + threadIdx.x;
    if (e >= N_EDGES) return;
    int d = s64 ? ew[2 * N_EDGES + 2 * e] : ew[N_EDGES + e];
    atomicAdd(&g_cnt[d], 1);
}

// ---------------- single-pass scan: off/cur/dinv + cnt re-zero + cleanup -------
__global__ void __launch_bounds__(1024) k_scan1() {
    int b = blockIdx.x, t = threadIdx.x;
    int i = b * 1024 + t;
    int lane = t & 31, wid = t >> 5;
    int c = (i < N_NODES) ? g_cnt[i] : 0;

    // warp inclusive scan
    int inc = c;
#pragma unroll
    for (int o = 1; o < 32; o <<= 1) {
        int u = __shfl_up_sync(0xffffffffu, inc, o);
        if (lane >= o) inc += u;
    }
    __shared__ int wpre[32];
    __shared__ int s_base;
    if (lane == 31) wpre[wid] = inc;
    __syncthreads();

    if (wid == 0) {
        int s = wpre[lane];
        int sinc = s;
#pragma unroll
        for (int o = 1; o < 32; o <<= 1) {
            int u = __shfl_up_sync(0xffffffffu, sinc, o);
            if (lane >= o) sinc += u;
        }
        wpre[lane] = sinc - s;           // exclusive warp prefix
        if (lane == 31) {                // sinc here = block aggregate
            g_scanval[b] = sinc;
            __threadfence();
            atomicExch(&g_scanflag[b], 1);
        }
    } else if (wid == 1) {
        // wait for all previous blocks' aggregates (all blocks resident: wave 1)
        int base = 0;
        for (int j = lane; j < b; j += 32) {
            while (atomicAdd(&g_scanflag[j], 0) == 0) {}
            __threadfence();
            base += *((volatile int*)(g_scanval + j));
        }
#pragma unroll
        for (int o = 16; o > 0; o >>= 1)
            base += __shfl_down_sync(0xffffffffu, base, o);
        if (lane == 0) s_base = base;
    }
    __syncthreads();

    if (i < N_NODES) {
        int exc = inc - c + wpre[wid] + s_base;
        g_off[i] = exc;
        g_cur[i] = exc;
        g_dinv[i] = rsqrtf((float)c + 1.0f);
        g_cnt[i] = 0;                    // ready for next call
    }
    if (b == 0 && t == 0) g_off[N_NODES] = N_EDGES;

    // cleanup: last finishing block resets flags + done (restores call state)
    __syncthreads();
    if (t == 0) {
        __threadfence();
        int d = atomicAdd(&g_done, 1);
        if (d == gridDim.x - 1) {
            for (int j = 0; j < SCAN_B; j++) g_scanflag[j] = 0;
            g_done = 0;
            __threadfence();
        }
    }
}

// ---------------- fill CSR (+ per-block detect) ----------------
__global__ void k_fill(const int* __restrict__ ew) {
    __shared__ int s64;
    if (threadIdx.x == 0) s64 = detect64_t0(ew);
    __syncthreads();
    int e = blockIdx.x * blockDim.x + threadIdx.x;
    if (e >= N_EDGES) return;
    int s, d;
    if (s64) {
        s = ew[2 * e];
        d = ew[2 * N_EDGES + 2 * e];
    } else {
        s = ew[e];
        d = ew[N_EDGES + e];
    }
    int slot = atomicAdd(&g_cur[d], 1);
    g_csr[slot] = s;
}

// ---------------- GEMM1: xws = fp16((x @ W1) * dinv) ----------------
__global__ void __launch_bounds__(256) k_gemm1(const float* __restrict__ x,
                                               const float* __restrict__ W) {
    __shared__ float4 ws[F_IN * (F_HID / 4)];
    int tid = threadIdx.x;
    for (int i = tid; i < F_IN * (F_HID / 4); i += 256)
        ws[i] = ((const float4*)W)[i];
    __syncthreads();

    int row = blockIdx.x * 256 + tid;
    if (row >= N_NODES) return;

    float4 acc[16];
#pragma unroll
    for (int j = 0; j < 16; j++) acc[j] = make_float4(0.f, 0.f, 0.f, 0.f);

    const float4* xr = (const float4*)(x + (size_t)row * F_IN);
#pragma unroll
    for (int kk = 0; kk < 16; kk++) {
        float4 xv = __ldg(xr + kk);
        float xs[4] = {xv.x, xv.y, xv.z, xv.w};
#pragma unroll
        for (int t = 0; t < 4; t++) {
            int k = kk * 4 + t;
            float xk = xs[t];
#pragma unroll
            for (int j = 0; j < 16; j++) {
                float4 w4 = ws[k * 16 + j];
                acc[j].x = fmaf(xk, w4.x, acc[j].x);
                acc[j].y = fmaf(xk, w4.y, acc[j].y);
                acc[j].z = fmaf(xk, w4.z, acc[j].z);
                acc[j].w = fmaf(xk, w4.w, acc[j].w);
            }
        }
    }
    float s = g_dinv[row];
    __half2 hrow[32];
#pragma unroll
    for (int j = 0; j < 16; j++) {
        hrow[2 * j]     = __floats2half2_rn(acc[j].x * s, acc[j].y * s);
        hrow[2 * j + 1] = __floats2half2_rn(acc[j].z * s, acc[j].w * s);
    }
    uint4* o = (uint4*)(g_xws + (size_t)row * F_HID);
    const uint4* hp = (const uint4*)hrow;
#pragma unroll
    for (int j = 0; j < 8; j++) o[j] = hp[j];
}

// ---------------- aggregate layer 1 + hidden epilogue (warp per node) ----------
__global__ void __launch_bounds__(256) k_agg1(const float* __restrict__ b1) {
    int node = (blockIdx.x * 256 + threadIdx.x) >> 5;
    int lane = threadIdx.x & 31;
    if (node >= N_NODES) return;

    int k   = g_off[node];
    int end = g_off[node + 1];
    int col = lane * 2;

    float2 acc0 = make_float2(0.f, 0.f);
    float2 acc1 = make_float2(0.f, 0.f);

    for (; k + 8 <= end; k += 8) {
        int idx[8];
#pragma unroll
        for (int j = 0; j < 8; j++) idx[j] = __ldg(g_csr + k + j);
        __half2 v[8];
#pragma unroll
        for (int j = 0; j < 8; j++)
            v[j] = *(const __half2*)(g_xws + (size_t)idx[j] * F_HID + col);
#pragma unroll
        for (int j = 0; j < 8; j += 2) {
            float2 f0 = __half22float2(v[j]);
            float2 f1 = __half22float2(v[j + 1]);
            acc0.x += f0.x; acc0.y += f0.y;
            acc1.x += f1.x; acc1.y += f1.y;
        }
    }
    for (; k < end; k++) {
        int s = __ldg(g_csr + k);
        float2 f = __half22float2(*(const __half2*)(g_xws + (size_t)s * F_HID + col));
        acc0.x += f.x; acc0.y += f.y;
    }

    float2 self = __half22float2(*(const __half2*)(g_xws + (size_t)node * F_HID + col));
    float sc = g_dinv[node];
    float2 b = ((const float2*)b1)[lane];
    float2 r;
    r.x = fmaxf(sc * (acc0.x + acc1.x + self.x) + b.x, 0.f);
    r.y = fmaxf(sc * (acc0.y + acc1.y + self.y) + b.y, 0.f);
    *(float2*)(g_h + (size_t)node * F_HID + col) = r;
}

// ---------------- GEMM2: hws = fp16((h @ W2) * dinv) ----------------
__global__ void __launch_bounds__(256) k_gemm2(const float* __restrict__ W) {
    __shared__ float4 ws[F_HID * (F_OUT / 4)];
    int tid = threadIdx.x;
    for (int i = tid; i < F_HID * (F_OUT / 4); i += 256)
        ws[i] = ((const float4*)W)[i];
    __syncthreads();

    int row = blockIdx.x * 256 + tid;
    if (row >= N_NODES) return;

    float4 acc[8];
#pragma unroll
    for (int j = 0; j < 8; j++) acc[j] = make_float4(0.f, 0.f, 0.f, 0.f);

    const float4* hr = (const float4*)(g_h + (size_t)row * F_HID);
#pragma unroll
    for (int kk = 0; kk < 16; kk++) {
        float4 hv = __ldg(hr + kk);
        float hs[4] = {hv.x, hv.y, hv.z, hv.w};
#pragma unroll
        for (int t = 0; t < 4; t++) {
            int k = kk * 4 + t;
            float hk = hs[t];
#pragma unroll
            for (int j = 0; j < 8; j++) {
                float4 w4 = ws[k * 8 + j];
                acc[j].x = fmaf(hk, w4.x, acc[j].x);
                acc[j].y = fmaf(hk, w4.y, acc[j].y);
                acc[j].z = fmaf(hk, w4.z, acc[j].z);
                acc[j].w = fmaf(hk, w4.w, acc[j].w);
            }
        }
    }
    float s = g_dinv[row];
    __half2 hrow[16];
#pragma unroll
    for (int j = 0; j < 8; j++) {
        hrow[2 * j]     = __floats2half2_rn(acc[j].x * s, acc[j].y * s);
        hrow[2 * j + 1] = __floats2half2_rn(acc[j].z * s, acc[j].w * s);
    }
    uint4* o = (uint4*)(g_hws + (size_t)row * F_OUT);
    const uint4* hp = (const uint4*)hrow;
#pragma unroll
    for (int j = 0; j < 4; j++) o[j] = hp[j];
}

// ---------------- aggregate layer 2 + output epilogue (warp per node) ----------
__global__ void __launch_bounds__(256) k_agg2(const float* __restrict__ b2,
                                              float* __restrict__ out) {
    int node = (blockIdx.x * 256 + threadIdx.x) >> 5;
    int lane = threadIdx.x & 31;
    if (node >= N_NODES) return;

    int k   = g_off[node];
    int end = g_off[node + 1];

    float acc0 = 0.f, acc1 = 0.f;

    for (; k + 8 <= end; k += 8) {
        int idx[8];
#pragma unroll
        for (int j = 0; j < 8; j++) idx[j] = __ldg(g_csr + k + j);
        float v[8];
#pragma unroll
        for (int j = 0; j < 8; j++)
            v[j] = __half2float(g_hws[(size_t)idx[j] * F_OUT + lane]);
        acc0 += (v[0] + v[2]) + (v[4] + v[6]);
        acc1 += (v[1] + v[3]) + (v[5] + v[7]);
    }
    for (; k < end; k++) {
        int s = __ldg(g_csr + k);
        acc0 += __half2float(g_hws[(size_t)s * F_OUT + lane]);
    }

    float self = __half2float(g_hws[(size_t)node * F_OUT + lane]);
    float sc = g_dinv[node];
    out[(size_t)node * F_OUT + lane] = sc * (acc0 + acc1 + self) + b2[lane];
}

// ---------------- launch ----------------
extern "C" void kernel_launch(void* const* d_in, const int* in_sizes, int n_in,
                              void* d_out, int out_size) {
    const float* x  = (const float*)d_in[0];
    const int*   ew = (const int*)d_in[1];
    const float* W1 = (const float*)d_in[2];
    const float* b1 = (const float*)d_in[3];
    const float* W2 = (const float*)d_in[4];
    const float* b2 = (const float*)d_in[5];
    float* out = (float*)d_out;

    const int T = 256;

    k_hist<<<(N_EDGES + T - 1) / T, T>>>(ew);
    k_scan1<<<SCAN_B, 1024>>>();
    k_fill<<<(N_EDGES + T - 1) / T, T>>>(ew);

    k_gemm1<<<(N_NODES + T - 1) / T, T>>>(x, W1);
    k_agg1<<<(N_NODES * 32 + T - 1) / T, T>>>(b1);

    k_gemm2<<<(N_NODES + T - 1) / T, T>>>(W2);
    k_agg2<<<(N_NODES * 32 + T - 1) / T, T>>>(b2, out);
}

// round 8
// speedup vs baseline: 1.0403x; 1.0056x over previous
#include <cuda_runtime.h>
#include <cuda_fp16.h>
#include <stdint.h>

#define N_NODES 100000
#define N_EDGES 1600000
#define F_IN  64
#define F_HID 64
#define F_OUT 32

#define SCAN_B 98   // 98 * 1024 >= N_NODES; 98 <= 148 SMs -> single wave

// ---------------- static device scratch ----------------
__device__ float  g_dinv[N_NODES];
__device__ __half g_xws [N_NODES * F_HID];   // (x@W1)*dinv, fp16
__device__ float  g_h   [N_NODES * F_HID];   // relu hidden (fp32)
__device__ __half g_hws [N_NODES * F_OUT];   // (h@W2)*dinv, fp16
__device__ int    g_cnt [N_NODES];           // BSS-zero; re-zeroed each call by scan
__device__ int    g_off [N_NODES + 1];
__device__ int    g_cur [N_NODES];
__device__ int    g_csr [N_EDGES];
__device__ int    g_scanval [SCAN_B];
__device__ int    g_scanflag[SCAN_B];        // reset by last block
__device__ int    g_done;                    // reset by last block

// ---------------- packed f32x2 helpers ----------------
__device__ __forceinline__ unsigned long long pack2(float lo, float hi) {
    unsigned long long r;
    asm("mov.b64 %0, {%1, %2};" : "=l"(r) : "f"(lo), "f"(hi));
    return r;
}
__device__ __forceinline__ void unpack2(unsigned long long v, float& lo, float& hi) {
    asm("mov.b64 {%0, %1}, %2;" : "=f"(lo), "=f"(hi) : "l"(v));
}
__device__ __forceinline__ unsigned long long fma2(unsigned long long a,
                                                   unsigned long long b,
                                                   unsigned long long c) {
    unsigned long long d;
    asm("fma.rn.f32x2 %0, %1, %2, %3;" : "=l"(d) : "l"(a), "l"(b), "l"(c));
    return d;
}
__device__ __forceinline__ unsigned long long mul2(unsigned long long a,
                                                   unsigned long long b) {
    unsigned long long d;
    asm("mul.rn.f32x2 %0, %1, %2;" : "=l"(d) : "l"(a), "l"(b));
    return d;
}

// per-block inline dtype detection: int64 layout (values<2^31) => odd words zero
__device__ __forceinline__ int detect64_t0(const int* __restrict__ w) {
    int nz = 0;
#pragma unroll
    for (int j = 1; j < 16; j += 2) nz |= w[j];
    return nz == 0;
}

// ---------------- histogram over dst (+ per-block detect) ----------------
__global__ void k_hist(const int* __restrict__ ew) {
    __shared__ int s64;
    if (threadIdx.x == 0) s64 = detect64_t0(ew);
    __syncthreads();
    int e = blockIdx.x * blockDim.x + threadIdx.x;
    if (e >= N_EDGES) return;
    int d = s64 ? ew[2 * N_EDGES + 2 * e] : ew[N_EDGES + e];
    atomicAdd(&g_cnt[d], 1);
}

// ---------------- single-pass scan: off/cur/dinv + cnt re-zero + cleanup -------
__global__ void __launch_bounds__(1024) k_scan1() {
    int b = blockIdx.x, t = threadIdx.x;
    int i = b * 1024 + t;
    int lane = t & 31, wid = t >> 5;
    int c = (i < N_NODES) ? g_cnt[i] : 0;

    int inc = c;
#pragma unroll
    for (int o = 1; o < 32; o <<= 1) {
        int u = __shfl_up_sync(0xffffffffu, inc, o);
        if (lane >= o) inc += u;
    }
    __shared__ int wpre[32];
    __shared__ int s_base;
    if (lane == 31) wpre[wid] = inc;
    __syncthreads();

    if (wid == 0) {
        int s = wpre[lane];
        int sinc = s;
#pragma unroll
        for (int o = 1; o < 32; o <<= 1) {
            int u = __shfl_up_sync(0xffffffffu, sinc, o);
            if (lane >= o) sinc += u;
        }
        wpre[lane] = sinc - s;
        if (lane == 31) {
            g_scanval[b] = sinc;
            __threadfence();
            atomicExch(&g_scanflag[b], 1);
        }
    } else if (wid == 1) {
        int base = 0;
        for (int j = lane; j < b; j += 32) {
            while (atomicAdd(&g_scanflag[j], 0) == 0) {}
            __threadfence();
            base += *((volatile int*)(g_scanval + j));
        }
#pragma unroll
        for (int o = 16; o > 0; o >>= 1)
            base += __shfl_down_sync(0xffffffffu, base, o);
        if (lane == 0) s_base = base;
    }
    __syncthreads();

    if (i < N_NODES) {
        int exc = inc - c + wpre[wid] + s_base;
        g_off[i] = exc;
        g_cur[i] = exc;
        g_dinv[i] = rsqrtf((float)c + 1.0f);
        g_cnt[i] = 0;
    }
    if (b == 0 && t == 0) g_off[N_NODES] = N_EDGES;

    __syncthreads();
    if (t == 0) {
        __threadfence();
        int d = atomicAdd(&g_done, 1);
        if (d == gridDim.x - 1) {
            for (int j = 0; j < SCAN_B; j++) g_scanflag[j] = 0;
            g_done = 0;
            __threadfence();
        }
    }
}

// ---------------- fill CSR (+ per-block detect) ----------------
__global__ void k_fill(const int* __restrict__ ew) {
    __shared__ int s64;
    if (threadIdx.x == 0) s64 = detect64_t0(ew);
    __syncthreads();
    int e = blockIdx.x * blockDim.x + threadIdx.x;
    if (e >= N_EDGES) return;
    int s, d;
    if (s64) {
        s = ew[2 * e];
        d = ew[2 * N_EDGES + 2 * e];
    } else {
        s = ew[e];
        d = ew[N_EDGES + e];
    }
    int slot = atomicAdd(&g_cur[d], 1);
    g_csr[slot] = s;
}

// ---------------- GEMM1: xws = fp16((x @ W1) * dinv), f32x2 packed ----------
__global__ void __launch_bounds__(256) k_gemm1(const float* __restrict__ x,
                                               const float* __restrict__ W) {
    __shared__ float4 ws[F_IN * (F_HID / 4)];  // 16KB
    int tid = threadIdx.x;
    for (int i = tid; i < F_IN * (F_HID / 4); i += 256)
        ws[i] = ((const float4*)W)[i];
    __syncthreads();

    int row = blockIdx.x * 256 + tid;
    if (row >= N_NODES) return;

    unsigned long long acc[32];   // 32 f32x2 pairs = 64 outputs
#pragma unroll
    for (int j = 0; j < 32; j++) acc[j] = 0ull;

    const float4* xr = (const float4*)(x + (size_t)row * F_IN);
#pragma unroll
    for (int kk = 0; kk < 16; kk++) {
        float4 xv = __ldg(xr + kk);
        float xs[4] = {xv.x, xv.y, xv.z, xv.w};
#pragma unroll
        for (int t = 0; t < 4; t++) {
            int k = kk * 4 + t;
            unsigned long long xk2 = pack2(xs[t], xs[t]);
#pragma unroll
            for (int j = 0; j < 16; j++) {
                float4 w4 = ws[k * 16 + j];
                acc[2 * j]     = fma2(xk2, pack2(w4.x, w4.y), acc[2 * j]);
                acc[2 * j + 1] = fma2(xk2, pack2(w4.z, w4.w), acc[2 * j + 1]);
            }
        }
    }
    float s = g_dinv[row];
    unsigned long long s2 = pack2(s, s);
    __half2 hrow[32];
#pragma unroll
    for (int j = 0; j < 32; j++) {
        float lo, hi;
        unpack2(mul2(acc[j], s2), lo, hi);
        hrow[j] = __floats2half2_rn(lo, hi);
    }
    uint4* o = (uint4*)(g_xws + (size_t)row * F_HID);
    const uint4* hp = (const uint4*)hrow;
#pragma unroll
    for (int j = 0; j < 8; j++) o[j] = hp[j];
}

// ---------------- aggregate layer 1 + hidden epilogue (warp per node) ----------
__global__ void __launch_bounds__(256) k_agg1(const float* __restrict__ b1) {
    int node = (blockIdx.x * 256 + threadIdx.x) >> 5;
    int lane = threadIdx.x & 31;
    if (node >= N_NODES) return;

    int k   = g_off[node];
    int end = g_off[node + 1];
    int col = lane * 2;

    float2 acc0 = make_float2(0.f, 0.f);
    float2 acc1 = make_float2(0.f, 0.f);

    for (; k + 8 <= end; k += 8) {
        int idx[8];
#pragma unroll
        for (int j = 0; j < 8; j++) idx[j] = __ldg(g_csr + k + j);
        __half2 v[8];
#pragma unroll
        for (int j = 0; j < 8; j++)
            v[j] = *(const __half2*)(g_xws + (size_t)idx[j] * F_HID + col);
#pragma unroll
        for (int j = 0; j < 8; j += 2) {
            float2 f0 = __half22float2(v[j]);
            float2 f1 = __half22float2(v[j + 1]);
            acc0.x += f0.x; acc0.y += f0.y;
            acc1.x += f1.x; acc1.y += f1.y;
        }
    }
    for (; k < end; k++) {
        int s = __ldg(g_csr + k);
        float2 f = __half22float2(*(const __half2*)(g_xws + (size_t)s * F_HID + col));
        acc0.x += f.x; acc0.y += f.y;
    }

    float2 self = __half22float2(*(const __half2*)(g_xws + (size_t)node * F_HID + col));
    float sc = g_dinv[node];
    float2 b = ((const float2*)b1)[lane];
    float2 r;
    r.x = fmaxf(sc * (acc0.x + acc1.x + self.x) + b.x, 0.f);
    r.y = fmaxf(sc * (acc0.y + acc1.y + self.y) + b.y, 0.f);
    *(float2*)(g_h + (size_t)node * F_HID + col) = r;
}

// ---------------- GEMM2: hws = fp16((h @ W2) * dinv), f32x2 packed ----------
__global__ void __launch_bounds__(256) k_gemm2(const float* __restrict__ W) {
    __shared__ float4 ws[F_HID * (F_OUT / 4)];  // 8KB
    int tid = threadIdx.x;
    for (int i = tid; i < F_HID * (F_OUT / 4); i += 256)
        ws[i] = ((const float4*)W)[i];
    __syncthreads();

    int row = blockIdx.x * 256 + tid;
    if (row >= N_NODES) return;

    unsigned long long acc[16];   // 16 f32x2 pairs = 32 outputs
#pragma unroll
    for (int j = 0; j < 16; j++) acc[j] = 0ull;

    const float4* hr = (const float4*)(g_h + (size_t)row * F_HID);
#pragma unroll
    for (int kk = 0; kk < 16; kk++) {
        float4 hv = __ldg(hr + kk);
        float hs[4] = {hv.x, hv.y, hv.z, hv.w};
#pragma unroll
        for (int t = 0; t < 4; t++) {
            int k = kk * 4 + t;
            unsigned long long hk2 = pack2(hs[t], hs[t]);
#pragma unroll
            for (int j = 0; j < 8; j++) {
                float4 w4 = ws[k * 8 + j];
                acc[2 * j]     = fma2(hk2, pack2(w4.x, w4.y), acc[2 * j]);
                acc[2 * j + 1] = fma2(hk2, pack2(w4.z, w4.w), acc[2 * j + 1]);
            }
        }
    }
    float s = g_dinv[row];
    unsigned long long s2 = pack2(s, s);
    __half2 hrow[16];
#pragma unroll
    for (int j = 0; j < 16; j++) {
        float lo, hi;
        unpack2(mul2(acc[j], s2), lo, hi);
        hrow[j] = __floats2half2_rn(lo, hi);
    }
    uint4* o = (uint4*)(g_hws + (size_t)row * F_OUT);
    const uint4* hp = (const uint4*)hrow;
#pragma unroll
    for (int j = 0; j < 4; j++) o[j] = hp[j];
}

// ---------------- aggregate layer 2 + output epilogue (warp per node) ----------
__global__ void __launch_bounds__(256) k_agg2(const float* __restrict__ b2,
                                              float* __restrict__ out) {
    int node = (blockIdx.x * 256 + threadIdx.x) >> 5;
    int lane = threadIdx.x & 31;
    if (node >= N_NODES) return;

    int k   = g_off[node];
    int end = g_off[node + 1];

    float acc0 = 0.f, acc1 = 0.f;

    for (; k + 8 <= end; k += 8) {
        int idx[8];
#pragma unroll
        for (int j = 0; j < 8; j++) idx[j] = __ldg(g_csr + k + j);
        float v[8];
#pragma unroll
        for (int j = 0; j < 8; j++)
            v[j] = __half2float(g_hws[(size_t)idx[j] * F_OUT + lane]);
        acc0 += (v[0] + v[2]) + (v[4] + v[6]);
        acc1 += (v[1] + v[3]) + (v[5] + v[7]);
    }
    for (; k < end; k++) {
        int s = __ldg(g_csr + k);
        acc0 += __half2float(g_hws[(size_t)s * F_OUT + lane]);
    }

    float self = __half2float(g_hws[(size_t)node * F_OUT + lane]);
    float sc = g_dinv[node];
    out[(size_t)node * F_OUT + lane] = sc * (acc0 + acc1 + self) + b2[lane];
}

// ---------------- launch ----------------
extern "C" void kernel_launch(void* const* d_in, const int* in_sizes, int n_in,
                              void* d_out, int out_size) {
    const float* x  = (const float*)d_in[0];
    const int*   ew = (const int*)d_in[1];
    const float* W1 = (const float*)d_in[2];
    const float* b1 = (const float*)d_in[3];
    const float* W2 = (const float*)d_in[4];
    const float* b2 = (const float*)d_in[5];
    float* out = (float*)d_out;

    const int T = 256;

    k_hist<<<(N_EDGES + T - 1) / T, T>>>(ew);
    k_scan1<<<SCAN_B, 1024>>>();
    k_fill<<<(N_EDGES + T - 1) / T, T>>>(ew);

    k_gemm1<<<(N_NODES + T - 1) / T, T>>>(x, W1);
    k_agg1<<<(N_NODES * 32 + T - 1) / T, T>>>(b1);

    k_gemm2<<<(N_NODES + T - 1) / T, T>>>(W2);
    k_agg2<<<(N_NODES * 32 + T - 1) / T, T>>>(b2, out);
}

// round 9
// speedup vs baseline: 1.0611x; 1.0200x over previous
#include <cuda_runtime.h>
#include <cuda_fp16.h>
#include <stdint.h>

#define N_NODES 100000
#define N_EDGES 1600000
#define F_IN  64
#define F_HID 64
#define F_OUT 32

#define SCAN_B 98   // 98 * 1024 >= N_NODES; single wave on 148 SMs

typedef unsigned long long ull;

// ---------------- static device scratch ----------------
__device__ float  g_dinv[N_NODES];
__device__ __half g_xws [N_NODES * F_HID];   // (x@W1)*dinv, fp16
__device__ float  g_h   [N_NODES * F_HID];   // relu hidden (fp32)
__device__ __half g_hws [N_NODES * F_OUT];   // (h@W2)*dinv, fp16
__device__ int    g_cnt [N_NODES];           // BSS-zero; re-zeroed each call
__device__ int    g_off [N_NODES + 1];
__device__ int    g_cur [N_NODES];
__device__ int    g_csr [N_EDGES];
__device__ int    g_scanval [SCAN_B];
__device__ int    g_scanflag[SCAN_B];
__device__ int    g_done;

// ---------------- packed f32x2 helpers ----------------
__device__ __forceinline__ ull pack2(float lo, float hi) {
    ull r; asm("mov.b64 %0, {%1, %2};" : "=l"(r) : "f"(lo), "f"(hi)); return r;
}
__device__ __forceinline__ void unpack2(ull v, float& lo, float& hi) {
    asm("mov.b64 {%0, %1}, %2;" : "=f"(lo), "=f"(hi) : "l"(v));
}
__device__ __forceinline__ ull fma2(ull a, ull b, ull c) {
    ull d; asm("fma.rn.f32x2 %0, %1, %2, %3;" : "=l"(d) : "l"(a), "l"(b), "l"(c)); return d;
}
__device__ __forceinline__ ull mul2(ull a, ull b) {
    ull d; asm("mul.rn.f32x2 %0, %1, %2;" : "=l"(d) : "l"(a), "l"(b)); return d;
}

// dtype detection: int64 layout (values<2^31) => odd words zero
__device__ __forceinline__ int detect64_t0(const int* __restrict__ w) {
    int nz = 0;
#pragma unroll
    for (int j = 1; j < 16; j += 2) nz |= w[j];
    return nz == 0;
}

// ---------------- histogram over dst ----------------
__global__ void k_hist(const int* __restrict__ ew) {
    __shared__ int s64;
    if (threadIdx.x == 0) s64 = detect64_t0(ew);
    __syncthreads();
    int e = blockIdx.x * blockDim.x + threadIdx.x;
    if (e >= N_EDGES) return;
    int d = s64 ? ew[2 * N_EDGES + 2 * e] : ew[N_EDGES + e];
    atomicAdd(&g_cnt[d], 1);
}

// ---------------- single-pass scan ----------------
__global__ void __launch_bounds__(1024) k_scan1() {
    int b = blockIdx.x, t = threadIdx.x;
    int i = b * 1024 + t;
    int lane = t & 31, wid = t >> 5;
    int c = (i < N_NODES) ? g_cnt[i] : 0;

    int inc = c;
#pragma unroll
    for (int o = 1; o < 32; o <<= 1) {
        int u = __shfl_up_sync(0xffffffffu, inc, o);
        if (lane >= o) inc += u;
    }
    __shared__ int wpre[32];
    __shared__ int s_base;
    if (lane == 31) wpre[wid] = inc;
    __syncthreads();

    if (wid == 0) {
        int s = wpre[lane];
        int sinc = s;
#pragma unroll
        for (int o = 1; o < 32; o <<= 1) {
            int u = __shfl_up_sync(0xffffffffu, sinc, o);
            if (lane >= o) sinc += u;
        }
        wpre[lane] = sinc - s;
        if (lane == 31) {
            g_scanval[b] = sinc;
            __threadfence();
            atomicExch(&g_scanflag[b], 1);
        }
    } else if (wid == 1) {
        int base = 0;
        for (int j = lane; j < b; j += 32) {
            while (atomicAdd(&g_scanflag[j], 0) == 0) {}
            __threadfence();
            base += *((volatile int*)(g_scanval + j));
        }
#pragma unroll
        for (int o = 16; o > 0; o >>= 1)
            base += __shfl_down_sync(0xffffffffu, base, o);
        if (lane == 0) s_base = base;
    }
    __syncthreads();

    if (i < N_NODES) {
        int exc = inc - c + wpre[wid] + s_base;
        g_off[i] = exc;
        g_cur[i] = exc;
        g_dinv[i] = rsqrtf((float)c + 1.0f);
        g_cnt[i] = 0;
    }
    if (b == 0 && t == 0) g_off[N_NODES] = N_EDGES;

    __syncthreads();
    if (t == 0) {
        __threadfence();
        int d = atomicAdd(&g_done, 1);
        if (d == gridDim.x - 1) {
            for (int j = 0; j < SCAN_B; j++) g_scanflag[j] = 0;
            g_done = 0;
            __threadfence();
        }
    }
}

// ---------------- fill CSR ----------------
__global__ void k_fill(const int* __restrict__ ew) {
    __shared__ int s64;
    if (threadIdx.x == 0) s64 = detect64_t0(ew);
    __syncthreads();
    int e = blockIdx.x * blockDim.x + threadIdx.x;
    if (e >= N_EDGES) return;
    int s, d;
    if (s64) {
        s = ew[2 * e];
        d = ew[2 * N_EDGES + 2 * e];
    } else {
        s = ew[e];
        d = ew[N_EDGES + e];
    }
    int slot = atomicAdd(&g_cur[d], 1);
    g_csr[slot] = s;
}

// ---------------- GEMM1: register-tiled RM=4 x RN=16, f32x2 ----------------
// block: 256 rows, 256 threads; rg=tid>>2 (row quad), cg=tid&3 (16-col group)
__global__ void __launch_bounds__(256) k_gemm1(const float* __restrict__ x,
                                               const float* __restrict__ W) {
    __shared__ float4 ws[F_IN][F_HID / 4];  // 16KB
    int tid = threadIdx.x;
    for (int i = tid; i < F_IN * (F_HID / 4); i += 256)
        ((float4*)ws)[i] = ((const float4*)W)[i];
    __syncthreads();

    int rg = tid >> 2, cg = tid & 3;
    int row0 = blockIdx.x * 256 + rg * 4;
    if (row0 >= N_NODES) return;

    int r[4];
#pragma unroll
    for (int i = 0; i < 4; i++) r[i] = min(row0 + i, N_NODES - 1);

    ull acc[4][8];
#pragma unroll
    for (int i = 0; i < 4; i++)
#pragma unroll
        for (int j = 0; j < 8; j++) acc[i][j] = 0ull;

#pragma unroll 4
    for (int kk = 0; kk < 16; kk++) {
        float4 xv[4];
#pragma unroll
        for (int i = 0; i < 4; i++)
            xv[i] = __ldg((const float4*)(x + (size_t)r[i] * F_IN) + kk);
        float xs[4][4];
#pragma unroll
        for (int i = 0; i < 4; i++) {
            xs[i][0] = xv[i].x; xs[i][1] = xv[i].y;
            xs[i][2] = xv[i].z; xs[i][3] = xv[i].w;
        }
#pragma unroll
        for (int t = 0; t < 4; t++) {
            int k = kk * 4 + t;
            ull wp[8];
#pragma unroll
            for (int j = 0; j < 4; j++) {
                float4 w4 = ws[k][cg * 4 + j];
                wp[2 * j]     = pack2(w4.x, w4.y);
                wp[2 * j + 1] = pack2(w4.z, w4.w);
            }
#pragma unroll
            for (int i = 0; i < 4; i++) {
                ull xk2 = pack2(xs[i][t], xs[i][t]);
#pragma unroll
                for (int j = 0; j < 8; j++)
                    acc[i][j] = fma2(xk2, wp[j], acc[i][j]);
            }
        }
    }

#pragma unroll
    for (int i = 0; i < 4; i++) {
        int row = row0 + i;
        if (row >= N_NODES) break;
        float s = g_dinv[row];
        ull s2 = pack2(s, s);
        __half2 hrow[8];
#pragma unroll
        for (int j = 0; j < 8; j++) {
            float lo, hi;
            unpack2(mul2(acc[i][j], s2), lo, hi);
            hrow[j] = __floats2half2_rn(lo, hi);
        }
        uint4* o = (uint4*)(g_xws + (size_t)row * F_HID + cg * 16);
        const uint4* hp = (const uint4*)hrow;
        o[0] = hp[0];
        o[1] = hp[1];
    }
}

// ---------------- aggregate layer 1 + hidden epilogue (warp per node) ----------
__global__ void __launch_bounds__(256) k_agg1(const float* __restrict__ b1) {
    int node = (blockIdx.x * 256 + threadIdx.x) >> 5;
    int lane = threadIdx.x & 31;
    if (node >= N_NODES) return;

    int k   = g_off[node];
    int end = g_off[node + 1];
    int col = lane * 2;

    float2 acc0 = make_float2(0.f, 0.f);
    float2 acc1 = make_float2(0.f, 0.f);

    for (; k + 8 <= end; k += 8) {
        int idx[8];
#pragma unroll
        for (int j = 0; j < 8; j++) idx[j] = __ldg(g_csr + k + j);
        __half2 v[8];
#pragma unroll
        for (int j = 0; j < 8; j++)
            v[j] = *(const __half2*)(g_xws + (size_t)idx[j] * F_HID + col);
#pragma unroll
        for (int j = 0; j < 8; j += 2) {
            float2 f0 = __half22float2(v[j]);
            float2 f1 = __half22float2(v[j + 1]);
            acc0.x += f0.x; acc0.y += f0.y;
            acc1.x += f1.x; acc1.y += f1.y;
        }
    }
    for (; k < end; k++) {
        int s = __ldg(g_csr + k);
        float2 f = __half22float2(*(const __half2*)(g_xws + (size_t)s * F_HID + col));
        acc0.x += f.x; acc0.y += f.y;
    }

    float2 self = __half22float2(*(const __half2*)(g_xws + (size_t)node * F_HID + col));
    float sc = g_dinv[node];
    float2 b = ((const float2*)b1)[lane];
    float2 r;
    r.x = fmaxf(sc * (acc0.x + acc1.x + self.x) + b.x, 0.f);
    r.y = fmaxf(sc * (acc0.y + acc1.y + self.y) + b.y, 0.f);
    *(float2*)(g_h + (size_t)node * F_HID + col) = r;
}

// ---------------- GEMM2: register-tiled RM=4 x RN=16, f32x2 ----------------
// block: 512 rows, 256 threads; rg=tid>>1, cg=tid&1
__global__ void __launch_bounds__(256) k_gemm2(const float* __restrict__ W) {
    __shared__ float4 ws[F_HID][F_OUT / 4];  // 8KB
    int tid = threadIdx.x;
    for (int i = tid; i < F_HID * (F_OUT / 4); i += 256)
        ((float4*)ws)[i] = ((const float4*)W)[i];
    __syncthreads();

    int rg = tid >> 1, cg = tid & 1;
    int row0 = blockIdx.x * 512 + rg * 4;
    if (row0 >= N_NODES) return;

    int r[4];
#pragma unroll
    for (int i = 0; i < 4; i++) r[i] = min(row0 + i, N_NODES - 1);

    ull acc[4][8];
#pragma unroll
    for (int i = 0; i < 4; i++)
#pragma unroll
        for (int j = 0; j < 8; j++) acc[i][j] = 0ull;

#pragma unroll 4
    for (int kk = 0; kk < 16; kk++) {
        float4 hv[4];
#pragma unroll
        for (int i = 0; i < 4; i++)
            hv[i] = __ldg((const float4*)(g_h + (size_t)r[i] * F_HID) + kk);
        float hs[4][4];
#pragma unroll
        for (int i = 0; i < 4; i++) {
            hs[i][0] = hv[i].x; hs[i][1] = hv[i].y;
            hs[i][2] = hv[i].z; hs[i][3] = hv[i].w;
        }
#pragma unroll
        for (int t = 0; t < 4; t++) {
            int k = kk * 4 + t;
            ull wp[8];
#pragma unroll
            for (int j = 0; j < 4; j++) {
                float4 w4 = ws[k][cg * 4 + j];
                wp[2 * j]     = pack2(w4.x, w4.y);
                wp[2 * j + 1] = pack2(w4.z, w4.w);
            }
#pragma unroll
            for (int i = 0; i < 4; i++) {
                ull hk2 = pack2(hs[i][t], hs[i][t]);
#pragma unroll
                for (int j = 0; j < 8; j++)
                    acc[i][j] = fma2(hk2, wp[j], acc[i][j]);
            }
        }
    }

#pragma unroll
    for (int i = 0; i < 4; i++) {
        int row = row0 + i;
        if (row >= N_NODES) break;
        float s = g_dinv[row];
        ull s2 = pack2(s, s);
        __half2 hrow[8];
#pragma unroll
        for (int j = 0; j < 8; j++) {
            float lo, hi;
            unpack2(mul2(acc[i][j], s2), lo, hi);
            hrow[j] = __floats2half2_rn(lo, hi);
        }
        uint4* o = (uint4*)(g_hws + (size_t)row * F_OUT + cg * 16);
        const uint4* hp = (const uint4*)hrow;
        o[0] = hp[0];
        o[1] = hp[1];
    }
}

// ---------------- aggregate layer 2 + output epilogue (warp per node) ----------
__global__ void __launch_bounds__(256) k_agg2(const float* __restrict__ b2,
                                              float* __restrict__ out) {
    int node = (blockIdx.x * 256 + threadIdx.x) >> 5;
    int lane = threadIdx.x & 31;
    if (node >= N_NODES) return;

    int k   = g_off[node];
    int end = g_off[node + 1];

    float acc0 = 0.f, acc1 = 0.f;

    for (; k + 8 <= end; k += 8) {
        int idx[8];
#pragma unroll
        for (int j = 0; j < 8; j++) idx[j] = __ldg(g_csr + k + j);
        float v[8];
#pragma unroll
        for (int j = 0; j < 8; j++)
            v[j] = __half2float(g_hws[(size_t)idx[j] * F_OUT + lane]);
        acc0 += (v[0] + v[2]) + (v[4] + v[6]);
        acc1 += (v[1] + v[3]) + (v[5] + v[7]);
    }
    for (; k < end; k++) {
        int s = __ldg(g_csr + k);
        acc0 += __half2float(g_hws[(size_t)s * F_OUT + lane]);
    }

    float self = __half2float(g_hws[(size_t)node * F_OUT + lane]);
    float sc = g_dinv[node];
    out[(size_t)node * F_OUT + lane] = sc * (acc0 + acc1 + self) + b2[lane];
}

// ---------------- launch ----------------
extern "C" void kernel_launch(void* const* d_in, const int* in_sizes, int n_in,
                              void* d_out, int out_size) {
    const float* x  = (const float*)d_in[0];
    const int*   ew = (const int*)d_in[1];
    const float* W1 = (const float*)d_in[2];
    const float* b1 = (const float*)d_in[3];
    const float* W2 = (const float*)d_in[4];
    const float* b2 = (const float*)d_in[5];
    float* out = (float*)d_out;

    const int T = 256;

    k_hist<<<(N_EDGES + T - 1) / T, T>>>(ew);
    k_scan1<<<SCAN_B, 1024>>>();
    k_fill<<<(N_EDGES + T - 1) / T, T>>>(ew);

    k_gemm1<<<(N_NODES + 255) / 256, T>>>(x, W1);
    k_agg1<<<(N_NODES * 32 + T - 1) / T, T>>>(b1);

    k_gemm2<<<(N_NODES + 511) / 512, T>>>(W2);
    k_agg2<<<(N_NODES * 32 + T - 1) / T, T>>>(b2, out);
}